// round 1
// baseline (speedup 1.0000x reference)
#include <cuda_runtime.h>
#include <cstdint>

#define BB 16
#define LL0 1024
#define LL1 3136
#define CC 768
#define HH 8
#define LOG2E 1.4426950408889634f

typedef unsigned long long u64;

__device__ __forceinline__ u64 pack2(float lo, float hi) {
    u64 r; asm("mov.b64 %0, {%1,%2};" : "=l"(r) : "f"(lo), "f"(hi)); return r;
}
__device__ __forceinline__ void unpack2(u64 v, float& lo, float& hi) {
    asm("mov.b64 {%0,%1}, %2;" : "=f"(lo), "=f"(hi) : "l"(v));
}
__device__ __forceinline__ u64 fma2(u64 a, u64 b, u64 c) {
    u64 d; asm("fma.rn.f32x2 %0,%1,%2,%3;" : "=l"(d) : "l"(a), "l"(b), "l"(c)); return d;
}
__device__ __forceinline__ u64 mul2(u64 a, u64 b) {
    u64 d; asm("mul.rn.f32x2 %0,%1,%2;" : "=l"(d) : "l"(a), "l"(b)); return d;
}
__device__ __forceinline__ u64 add2(u64 a, u64 b) {
    u64 d; asm("add.rn.f32x2 %0,%1,%2;" : "=l"(d) : "l"(a), "l"(b)); return d;
}
__device__ __forceinline__ float ex2f(float x) {
    float r; asm("ex2.approx.f32 %0, %1;" : "=f"(r) : "f"(x)); return r;
}
__device__ __forceinline__ float rcpf(float x) {
    float r; asm("rcp.approx.f32 %0, %1;" : "=f"(r) : "f"(x)); return r;
}

// ---------------- scratch (static device globals; no allocation) ----------------
__device__ float g_x0t[BB * LL0 * HH];       // x0 @ W00 + b00
__device__ float g_x1t[BB * LL1 * HH];       // x1 @ W01 + b01
__device__ float g_num0[4][BB * LL0 * HH];   // row-softmax numerator partials (m split 4)
__device__ float g_den0[4][BB * LL0];
__device__ float g_num1[2][BB * LL1 * HH];   // col-softmax numerator partials (l split 2)
__device__ float g_den1[2][BB * LL1];
__device__ float g_x10[BB * LL1 * HH];       // x1_0
__device__ float g_S0[BB * HH];              // fovea denominators for x0t
__device__ float g_S1[BB * HH];              // fovea denominators for x1_0
__device__ float g_x0o[BB * LL0 * HH];
__device__ float g_x1o[BB * LL1 * HH];

// ---------------- K1: input projections  x0t = x0@W00+b00, x1t = x1@W01+b01 ----------------
// warp processes 4 consecutive rows; W (both) cached in shared; packed-f32x2 accumulate.
__global__ void k_proj(const float* __restrict__ x,
                       const float* __restrict__ W00, const float* __restrict__ b00,
                       const float* __restrict__ W01, const float* __restrict__ b01) {
    __shared__ __align__(16) float sW[2 * CC * HH];  // 48KB
    const int tid = threadIdx.x;
    for (int i = tid; i < CC * HH; i += blockDim.x) {
        sW[i] = W00[i];
        sW[CC * HH + i] = W01[i];
    }
    __syncthreads();

    const int warp = blockIdx.x * 8 + (tid >> 5);
    const int lane = tid & 31;
    const int r0 = warp * 4;
    const int LT = LL0 + LL1;
    const int b = r0 / LT;
    const int i = r0 % LT;
    const bool is0 = (i < LL0);
    const float* Wp = is0 ? sW : sW + CC * HH;
    const float* xp = x + (size_t)r0 * CC;

    u64 acc[4][4];
#pragma unroll
    for (int r = 0; r < 4; r++)
#pragma unroll
        for (int p = 0; p < 4; p++) acc[r][p] = 0ull;

#pragma unroll
    for (int it = 0; it < 6; it++) {
        const int k = it * 128 + lane * 4;
        float4 xv[4];
#pragma unroll
        for (int r = 0; r < 4; r++) xv[r] = *(const float4*)(xp + (size_t)r * CC + k);
#pragma unroll
        for (int j = 0; j < 4; j++) {
            const u64* wq = (const u64*)(Wp + (k + j) * HH);
            const u64 w0 = wq[0], w1 = wq[1], w2 = wq[2], w3 = wq[3];
#pragma unroll
            for (int r = 0; r < 4; r++) {
                const float xs = (j == 0) ? xv[r].x : (j == 1) ? xv[r].y : (j == 2) ? xv[r].z : xv[r].w;
                const u64 xx = pack2(xs, xs);
                acc[r][0] = fma2(xx, w0, acc[r][0]);
                acc[r][1] = fma2(xx, w1, acc[r][1]);
                acc[r][2] = fma2(xx, w2, acc[r][2]);
                acc[r][3] = fma2(xx, w3, acc[r][3]);
            }
        }
    }
    // warp reduction
#pragma unroll
    for (int off = 16; off; off >>= 1)
#pragma unroll
        for (int r = 0; r < 4; r++)
#pragma unroll
            for (int p = 0; p < 4; p++)
                acc[r][p] = add2(acc[r][p], __shfl_xor_sync(0xffffffffu, acc[r][p], off));

    if (lane == 0) {
        const float* bias = is0 ? b00 : b01;
        float bv[8];
#pragma unroll
        for (int d = 0; d < 8; d++) bv[d] = bias[d];
        float* dst = is0 ? (g_x0t + ((size_t)b * LL0 + i) * HH)
                         : (g_x1t + ((size_t)b * LL1 + (i - LL0)) * HH);
#pragma unroll
        for (int r = 0; r < 4; r++) {
            float o[8];
#pragma unroll
            for (int p = 0; p < 4; p++) unpack2(acc[r][p], o[2 * p], o[2 * p + 1]);
#pragma unroll
            for (int d = 0; d < 8; d++) o[d] += bv[d];
            *(float4*)(dst + (size_t)r * HH) = make_float4(o[0], o[1], o[2], o[3]);
            *(float4*)(dst + (size_t)r * HH + 4) = make_float4(o[4], o[5], o[6], o[7]);
        }
    }
}

// ---------------- K2: row direction. S[l,m]=x0t[l].x1t[m]; num0[l]=sum_m e^S x1t[m]; den0[l]=sum e^S
// grid (8 l-chunks, 4 m-splits, 16 b), block 128 (thread = one l row)
__global__ void k_attn_row() {
    __shared__ __align__(16) float s1[784 * HH];  // one m-quarter of x1t for this batch
    const int b = blockIdx.z, ms = blockIdx.y, lc = blockIdx.x;
    const int tid = threadIdx.x;
    const float* src = g_x1t + ((size_t)b * LL1 + ms * 784) * HH;
    for (int i = tid; i < 784 * HH / 4; i += 128) ((float4*)s1)[i] = ((const float4*)src)[i];
    __syncthreads();

    const int l = lc * 128 + tid;
    const float* a = g_x0t + ((size_t)b * LL0 + l) * HH;
    u64 av[4];
#pragma unroll
    for (int p = 0; p < 4; p++) av[p] = pack2(a[2 * p] * LOG2E, a[2 * p + 1] * LOG2E);

    u64 num[4] = {0ull, 0ull, 0ull, 0ull};
    float den = 0.f;
#pragma unroll 4
    for (int m = 0; m < 784; m++) {
        const u64* q = (const u64*)(s1 + m * HH);
        const u64 p0 = q[0], p1 = q[1], p2 = q[2], p3 = q[3];
        u64 t0 = mul2(av[0], p0), t1 = mul2(av[1], p1);
        t0 = fma2(av[2], p2, t0);
        t1 = fma2(av[3], p3, t1);
        t0 = add2(t0, t1);
        float lo, hi;
        unpack2(t0, lo, hi);
        const float e = ex2f(lo + hi);
        const u64 ee = pack2(e, e);
        num[0] = fma2(ee, p0, num[0]);
        num[1] = fma2(ee, p1, num[1]);
        num[2] = fma2(ee, p2, num[2]);
        num[3] = fma2(ee, p3, num[3]);
        den += e;
    }
    float o[8];
#pragma unroll
    for (int p = 0; p < 4; p++) unpack2(num[p], o[2 * p], o[2 * p + 1]);
    float* nd = g_num0[ms] + ((size_t)b * LL0 + l) * HH;
    *(float4*)(nd) = make_float4(o[0], o[1], o[2], o[3]);
    *(float4*)(nd + 4) = make_float4(o[4], o[5], o[6], o[7]);
    g_den0[ms][b * LL0 + l] = den;
}

// ---------------- K3: col direction. num1[m]=sum_l e^S[l,m] x0t[l]; den1[m]=sum_l e^S[l,m]
// grid (13 m-chunks, 2 l-splits, 16 b), block 256 (thread = one m col)
__global__ void k_attn_col() {
    __shared__ __align__(16) float s0[512 * HH];  // one l-half of x0t
    const int b = blockIdx.z, ls = blockIdx.y, mc = blockIdx.x;
    const int tid = threadIdx.x;
    const float* src = g_x0t + ((size_t)b * LL0 + ls * 512) * HH;
    for (int i = tid; i < 512 * HH / 4; i += 256) ((float4*)s0)[i] = ((const float4*)src)[i];
    __syncthreads();

    const int m = mc * 256 + tid;
    const int mm = (m < LL1) ? m : (LL1 - 1);
    const float* a = g_x1t + ((size_t)b * LL1 + mm) * HH;
    u64 av[4];
#pragma unroll
    for (int p = 0; p < 4; p++) av[p] = pack2(a[2 * p] * LOG2E, a[2 * p + 1] * LOG2E);

    u64 num[4] = {0ull, 0ull, 0ull, 0ull};
    float den = 0.f;
#pragma unroll 4
    for (int l = 0; l < 512; l++) {
        const u64* q = (const u64*)(s0 + l * HH);
        const u64 p0 = q[0], p1 = q[1], p2 = q[2], p3 = q[3];
        u64 t0 = mul2(av[0], p0), t1 = mul2(av[1], p1);
        t0 = fma2(av[2], p2, t0);
        t1 = fma2(av[3], p3, t1);
        t0 = add2(t0, t1);
        float lo, hi;
        unpack2(t0, lo, hi);
        const float e = ex2f(lo + hi);
        const u64 ee = pack2(e, e);
        num[0] = fma2(ee, p0, num[0]);
        num[1] = fma2(ee, p1, num[1]);
        num[2] = fma2(ee, p2, num[2]);
        num[3] = fma2(ee, p3, num[3]);
        den += e;
    }
    if (m < LL1) {
        float o[8];
#pragma unroll
        for (int p = 0; p < 4; p++) unpack2(num[p], o[2 * p], o[2 * p + 1]);
        float* nd = g_num1[ls] + ((size_t)b * LL1 + m) * HH;
        *(float4*)(nd) = make_float4(o[0], o[1], o[2], o[3]);
        *(float4*)(nd + 4) = make_float4(o[4], o[5], o[6], o[7]);
        g_den1[ls][b * LL1 + m] = den;
    }
}

// ---------------- fovea denominators: S0[b,d] = sum_l exp(x0t[b,l,d]) ----------------
__global__ void k_sum0() {  // grid 16, block 256
    const int b = blockIdx.x, tid = threadIdx.x;
    float s[8] = {0, 0, 0, 0, 0, 0, 0, 0};
    for (int l = tid; l < LL0; l += 256) {
        const float4* p = (const float4*)(g_x0t + ((size_t)b * LL0 + l) * HH);
        const float4 v0 = p[0], v1 = p[1];
        s[0] += ex2f(v0.x * LOG2E); s[1] += ex2f(v0.y * LOG2E);
        s[2] += ex2f(v0.z * LOG2E); s[3] += ex2f(v0.w * LOG2E);
        s[4] += ex2f(v1.x * LOG2E); s[5] += ex2f(v1.y * LOG2E);
        s[6] += ex2f(v1.z * LOG2E); s[7] += ex2f(v1.w * LOG2E);
    }
    __shared__ float red[8][256];
#pragma unroll
    for (int d = 0; d < 8; d++) red[d][tid] = s[d];
    __syncthreads();
    for (int off = 128; off; off >>= 1) {
        if (tid < off)
#pragma unroll
            for (int d = 0; d < 8; d++) red[d][tid] += red[d][tid + off];
        __syncthreads();
    }
    if (tid < 8) g_S0[b * 8 + tid] = red[tid][0];
}

// ---------------- combine0: x0o = fovea(x0t) + x0_1 ----------------
__global__ void k_combine0() {  // grid (4, 16), block 256; thread = one l
    const int b = blockIdx.y;
    const int l = blockIdx.x * 256 + threadIdx.x;
    const size_t base = ((size_t)b * LL0 + l) * HH;
    float num[8] = {0, 0, 0, 0, 0, 0, 0, 0};
    float den = 0.f;
#pragma unroll
    for (int s = 0; s < 4; s++) {
        den += g_den0[s][b * LL0 + l];
        const float4* p = (const float4*)(g_num0[s] + base);
        const float4 v0 = p[0], v1 = p[1];
        num[0] += v0.x; num[1] += v0.y; num[2] += v0.z; num[3] += v0.w;
        num[4] += v1.x; num[5] += v1.y; num[6] += v1.z; num[7] += v1.w;
    }
    const float inv = rcpf(den);
    const float* xt = g_x0t + base;
    const float* S = g_S0 + b * 8;
    float o[8];
#pragma unroll
    for (int d = 0; d < 8; d++) {
        const float t = xt[d];
        o[d] = ex2f(t * LOG2E) * rcpf(S[d]) * t + num[d] * inv;
    }
    float* dst = g_x0o + base;
    *(float4*)(dst) = make_float4(o[0], o[1], o[2], o[3]);
    *(float4*)(dst + 4) = make_float4(o[4], o[5], o[6], o[7]);
}

// ---------------- reduce1: x1_0 = sum(num1)/sum(den1) ----------------
__global__ void k_reduce1() {  // grid (13, 16), block 256
    const int b = blockIdx.y;
    const int m = blockIdx.x * 256 + threadIdx.x;
    if (m >= LL1) return;
    const size_t base = ((size_t)b * LL1 + m) * HH;
    float num[8] = {0, 0, 0, 0, 0, 0, 0, 0};
    float den = 0.f;
#pragma unroll
    for (int s = 0; s < 2; s++) {
        den += g_den1[s][b * LL1 + m];
        const float4* p = (const float4*)(g_num1[s] + base);
        const float4 v0 = p[0], v1 = p[1];
        num[0] += v0.x; num[1] += v0.y; num[2] += v0.z; num[3] += v0.w;
        num[4] += v1.x; num[5] += v1.y; num[6] += v1.z; num[7] += v1.w;
    }
    const float inv = rcpf(den);
    float* dst = g_x10 + base;
    *(float4*)(dst) = make_float4(num[0] * inv, num[1] * inv, num[2] * inv, num[3] * inv);
    *(float4*)(dst + 4) = make_float4(num[4] * inv, num[5] * inv, num[6] * inv, num[7] * inv);
}

// ---------------- S1[b,d] = sum_m exp(x1_0[b,m,d]) ----------------
__global__ void k_sum1() {  // grid 16, block 256
    const int b = blockIdx.x, tid = threadIdx.x;
    float s[8] = {0, 0, 0, 0, 0, 0, 0, 0};
    for (int m = tid; m < LL1; m += 256) {
        const float4* p = (const float4*)(g_x10 + ((size_t)b * LL1 + m) * HH);
        const float4 v0 = p[0], v1 = p[1];
        s[0] += ex2f(v0.x * LOG2E); s[1] += ex2f(v0.y * LOG2E);
        s[2] += ex2f(v0.z * LOG2E); s[3] += ex2f(v0.w * LOG2E);
        s[4] += ex2f(v1.x * LOG2E); s[5] += ex2f(v1.y * LOG2E);
        s[6] += ex2f(v1.z * LOG2E); s[7] += ex2f(v1.w * LOG2E);
    }
    __shared__ float red[8][256];
#pragma unroll
    for (int d = 0; d < 8; d++) red[d][tid] = s[d];
    __syncthreads();
    for (int off = 128; off; off >>= 1) {
        if (tid < off)
#pragma unroll
            for (int d = 0; d < 8; d++) red[d][tid] += red[d][tid + off];
        __syncthreads();
    }
    if (tid < 8) g_S1[b * 8 + tid] = red[tid][0];
}

// ---------------- combine1: x1o = fovea(x1_0) + x1t ----------------
__global__ void k_combine1() {  // grid (13, 16), block 256
    const int b = blockIdx.y;
    const int m = blockIdx.x * 256 + threadIdx.x;
    if (m >= LL1) return;
    const size_t base = ((size_t)b * LL1 + m) * HH;
    const float* xt = g_x1t + base;
    const float* x10 = g_x10 + base;
    const float* S = g_S1 + b * 8;
    float o[8];
#pragma unroll
    for (int d = 0; d < 8; d++) {
        const float t = x10[d];
        o[d] = ex2f(t * LOG2E) * rcpf(S[d]) * t + xt[d];
    }
    float* dst = g_x1o + base;
    *(float4*)(dst) = make_float4(o[0], o[1], o[2], o[3]);
    *(float4*)(dst + 4) = make_float4(o[4], o[5], o[6], o[7]);
}

// ---------------- output projections, fused transpose: out[b,c,l] = x_o[b,l,:].W[:,c] + bias[c]
__global__ void k_out0(const float* __restrict__ W1, const float* __restrict__ b1,
                       float* __restrict__ out) {
    // grid (8 c-chunks, 8 l-chunks, 16 b), block 256 = 8 warps
    const int b = blockIdx.z, lcb = blockIdx.y, ccb = blockIdx.x;
    const int w = threadIdx.x >> 5, lane = threadIdx.x & 31;
    const int l0 = lcb * 128 + lane * 4;
    const float* xo = g_x0o + ((size_t)b * LL0 + l0) * HH;
    float xr[4][8];
#pragma unroll
    for (int r = 0; r < 4; r++) {
        const float4 v0 = *(const float4*)(xo + (size_t)r * HH);
        const float4 v1 = *(const float4*)(xo + (size_t)r * HH + 4);
        xr[r][0] = v0.x; xr[r][1] = v0.y; xr[r][2] = v0.z; xr[r][3] = v0.w;
        xr[r][4] = v1.x; xr[r][5] = v1.y; xr[r][6] = v1.z; xr[r][7] = v1.w;
    }
    float* ob = out + (size_t)b * CC * LL0;
    for (int j = 0; j < 12; j++) {
        const int c = ccb * 96 + w * 12 + j;
        float wv[8];
#pragma unroll
        for (int k = 0; k < 8; k++) wv[k] = __ldg(&W1[k * CC + c]);
        const float bias = __ldg(&b1[c]);
        float o[4];
#pragma unroll
        for (int r = 0; r < 4; r++) {
            float acc = bias;
#pragma unroll
            for (int k = 0; k < 8; k++) acc += xr[r][k] * wv[k];
            o[r] = acc;
        }
        *(float4*)(ob + (size_t)c * LL0 + l0) = make_float4(o[0], o[1], o[2], o[3]);
    }
}

__global__ void k_out1(const float* __restrict__ W2, const float* __restrict__ b2,
                       float* __restrict__ out) {
    // grid (8 c-chunks, 25 l-chunks, 16 b), block 256 = 8 warps
    const int b = blockIdx.z, lcb = blockIdx.y, ccb = blockIdx.x;
    const int w = threadIdx.x >> 5, lane = threadIdx.x & 31;
    const int l0 = lcb * 128 + lane * 4;
    const bool active = (l0 < LL1);
    float xr[4][8];
    if (active) {
        const float* xo = g_x1o + ((size_t)b * LL1 + l0) * HH;
#pragma unroll
        for (int r = 0; r < 4; r++) {
            const float4 v0 = *(const float4*)(xo + (size_t)r * HH);
            const float4 v1 = *(const float4*)(xo + (size_t)r * HH + 4);
            xr[r][0] = v0.x; xr[r][1] = v0.y; xr[r][2] = v0.z; xr[r][3] = v0.w;
            xr[r][4] = v1.x; xr[r][5] = v1.y; xr[r][6] = v1.z; xr[r][7] = v1.w;
        }
    }
    float* ob = out + (size_t)BB * CC * LL0 + (size_t)b * CC * LL1;
    for (int j = 0; j < 12; j++) {
        const int c = ccb * 96 + w * 12 + j;
        float wv[8];
#pragma unroll
        for (int k = 0; k < 8; k++) wv[k] = __ldg(&W2[k * CC + c]);
        const float bias = __ldg(&b2[c]);
        if (active) {
            float o[4];
#pragma unroll
            for (int r = 0; r < 4; r++) {
                float acc = bias;
#pragma unroll
                for (int k = 0; k < 8; k++) acc += xr[r][k] * wv[k];
                o[r] = acc;
            }
            *(float4*)(ob + (size_t)c * LL1 + l0) = make_float4(o[0], o[1], o[2], o[3]);
        }
    }
}

extern "C" void kernel_launch(void* const* d_in, const int* in_sizes, int n_in,
                              void* d_out, int out_size) {
    const float* x   = (const float*)d_in[0];
    const float* W00 = (const float*)d_in[1];
    const float* b00 = (const float*)d_in[2];
    const float* W01 = (const float*)d_in[3];
    const float* b01 = (const float*)d_in[4];
    const float* W1  = (const float*)d_in[5];
    const float* b1  = (const float*)d_in[6];
    const float* W2  = (const float*)d_in[7];
    const float* b2  = (const float*)d_in[8];
    float* out = (float*)d_out;

    k_proj<<<2080, 256>>>(x, W00, b00, W01, b01);
    k_attn_row<<<dim3(8, 4, 16), 128>>>();
    k_attn_col<<<dim3(13, 2, 16), 256>>>();
    k_sum0<<<16, 256>>>();
    k_combine0<<<dim3(4, 16), 256>>>();
    k_reduce1<<<dim3(13, 16), 256>>>();
    k_sum1<<<16, 256>>>();
    k_combine1<<<dim3(13, 16), 256>>>();
    k_out0<<<dim3(8, 8, 16), 256>>>(W1, b1, out);
    k_out1<<<dim3(8, 25, 16), 256>>>(W2, b2, out);
}

// round 2
// speedup vs baseline: 1.0885x; 1.0885x over previous
#include <cuda_runtime.h>
#include <cstdint>

#define BB 16
#define LL0 1024
#define LL1 3136
#define CC 768
#define HH 8
#define LOG2E 1.4426950408889634f

typedef unsigned long long u64;

__device__ __forceinline__ u64 pack2(float lo, float hi) {
    u64 r; asm("mov.b64 %0, {%1,%2};" : "=l"(r) : "f"(lo), "f"(hi)); return r;
}
__device__ __forceinline__ void unpack2(u64 v, float& lo, float& hi) {
    asm("mov.b64 {%0,%1}, %2;" : "=f"(lo), "=f"(hi) : "l"(v));
}
__device__ __forceinline__ u64 fma2(u64 a, u64 b, u64 c) {
    u64 d; asm("fma.rn.f32x2 %0,%1,%2,%3;" : "=l"(d) : "l"(a), "l"(b), "l"(c)); return d;
}
__device__ __forceinline__ u64 mul2(u64 a, u64 b) {
    u64 d; asm("mul.rn.f32x2 %0,%1,%2;" : "=l"(d) : "l"(a), "l"(b)); return d;
}
__device__ __forceinline__ u64 add2(u64 a, u64 b) {
    u64 d; asm("add.rn.f32x2 %0,%1,%2;" : "=l"(d) : "l"(a), "l"(b)); return d;
}
__device__ __forceinline__ float ex2f(float x) {
    float r; asm("ex2.approx.f32 %0, %1;" : "=f"(r) : "f"(x)); return r;
}
__device__ __forceinline__ float rcpf(float x) {
    float r; asm("rcp.approx.f32 %0, %1;" : "=f"(r) : "f"(x)); return r;
}

// ---------------- scratch ----------------
__device__ float g_x0t[BB * LL0 * HH];
__device__ float g_x1t[BB * LL1 * HH];
__device__ float g_num0[8][BB * LL0 * HH];   // row-softmax numerator partials (m split 8)
__device__ float g_den0[8][BB * LL0];
__device__ float g_num1[4][BB * LL1 * HH];   // col-softmax numerator partials (l split 4)
__device__ float g_den1[4][BB * LL1];
__device__ float g_x10[BB * LL1 * HH];
__device__ float g_S0[BB * HH];
__device__ float g_S1[BB * HH];
__device__ float g_x0o[BB * LL0 * HH];
__device__ float g_x1o[BB * LL1 * HH];

// ---------------- K0: zero the atomic accumulators ----------------
__global__ void k_zero() {
    const int t = threadIdx.x;
    if (t < BB * HH) g_S0[t] = 0.f;
    else if (t < 2 * BB * HH) g_S1[t - BB * HH] = 0.f;
}

// ---------------- K1: input projections (+ fused S0 exp-sum atomics) ----------------
__global__ void k_proj(const float* __restrict__ x,
                       const float* __restrict__ W00, const float* __restrict__ b00,
                       const float* __restrict__ W01, const float* __restrict__ b01) {
    __shared__ __align__(16) float sW[2 * CC * HH];  // 48KB
    const int tid = threadIdx.x;
    for (int i = tid; i < CC * HH; i += blockDim.x) {
        sW[i] = W00[i];
        sW[CC * HH + i] = W01[i];
    }
    __syncthreads();

    const int warp = blockIdx.x * 8 + (tid >> 5);
    const int lane = tid & 31;
    const int r0 = warp * 4;
    const int LT = LL0 + LL1;
    const int b = r0 / LT;
    const int i = r0 % LT;
    const bool is0 = (i < LL0);
    const float* Wp = is0 ? sW : sW + CC * HH;
    const float* xp = x + (size_t)r0 * CC;

    u64 acc[4][4];
#pragma unroll
    for (int r = 0; r < 4; r++)
#pragma unroll
        for (int p = 0; p < 4; p++) acc[r][p] = 0ull;

#pragma unroll
    for (int it = 0; it < 6; it++) {
        const int k = it * 128 + lane * 4;
        float4 xv[4];
#pragma unroll
        for (int r = 0; r < 4; r++) xv[r] = __ldcs((const float4*)(xp + (size_t)r * CC + k));
#pragma unroll
        for (int j = 0; j < 4; j++) {
            const u64* wq = (const u64*)(Wp + (k + j) * HH);
            const u64 w0 = wq[0], w1 = wq[1], w2 = wq[2], w3 = wq[3];
#pragma unroll
            for (int r = 0; r < 4; r++) {
                const float xs = (j == 0) ? xv[r].x : (j == 1) ? xv[r].y : (j == 2) ? xv[r].z : xv[r].w;
                const u64 xx = pack2(xs, xs);
                acc[r][0] = fma2(xx, w0, acc[r][0]);
                acc[r][1] = fma2(xx, w1, acc[r][1]);
                acc[r][2] = fma2(xx, w2, acc[r][2]);
                acc[r][3] = fma2(xx, w3, acc[r][3]);
            }
        }
    }
#pragma unroll
    for (int off = 16; off; off >>= 1)
#pragma unroll
        for (int r = 0; r < 4; r++)
#pragma unroll
            for (int p = 0; p < 4; p++)
                acc[r][p] = add2(acc[r][p], __shfl_xor_sync(0xffffffffu, acc[r][p], off));

    if (lane == 0) {
        const float* bias = is0 ? b00 : b01;
        float bv[8];
#pragma unroll
        for (int d = 0; d < 8; d++) bv[d] = bias[d];
        float* dst = is0 ? (g_x0t + ((size_t)b * LL0 + i) * HH)
                         : (g_x1t + ((size_t)b * LL1 + (i - LL0)) * HH);
        float se[8] = {0, 0, 0, 0, 0, 0, 0, 0};
#pragma unroll
        for (int r = 0; r < 4; r++) {
            float o[8];
#pragma unroll
            for (int p = 0; p < 4; p++) unpack2(acc[r][p], o[2 * p], o[2 * p + 1]);
#pragma unroll
            for (int d = 0; d < 8; d++) o[d] += bv[d];
            *(float4*)(dst + (size_t)r * HH) = make_float4(o[0], o[1], o[2], o[3]);
            *(float4*)(dst + (size_t)r * HH + 4) = make_float4(o[4], o[5], o[6], o[7]);
            if (is0) {
#pragma unroll
                for (int d = 0; d < 8; d++) se[d] += ex2f(o[d] * LOG2E);
            }
        }
        if (is0) {
#pragma unroll
            for (int d = 0; d < 8; d++) atomicAdd(&g_S0[b * 8 + d], se[d]);
        }
    }
}

// ---------------- K2: row direction, pair-packed.
// thread = one l, loops over a 392-wide m chunk in pairs; both logits land in the two f32x2 lanes.
// grid (4 lc, 8 ms, 16 b), block 256
__global__ void k_attn_row() {
    __shared__ __align__(16) u64 sT[196][8];  // (pair, d) -> (v[2i][d], v[2i+1][d]); 12.25KB
    const int b = blockIdx.z, ms = blockIdx.y, lc = blockIdx.x;
    const int tid = threadIdx.x;
    const float* src = g_x1t + ((size_t)b * LL1 + ms * 392) * HH;
    for (int m = tid; m < 392; m += 256) {
        const float4 v0 = *(const float4*)(src + m * 8);
        const float4 v1 = *(const float4*)(src + m * 8 + 4);
        float* f = (float*)&sT[m >> 1][0] + (m & 1);
        f[0] = v0.x; f[2] = v0.y; f[4] = v0.z; f[6] = v0.w;
        f[8] = v1.x; f[10] = v1.y; f[12] = v1.z; f[14] = v1.w;
    }
    __syncthreads();

    const int l = lc * 256 + tid;
    const float* a = g_x0t + ((size_t)b * LL0 + l) * HH;
    u64 av[8];
#pragma unroll
    for (int d = 0; d < 8; d++) { const float s = a[d] * LOG2E; av[d] = pack2(s, s); }

    u64 acc[8] = {0ull, 0ull, 0ull, 0ull, 0ull, 0ull, 0ull, 0ull};
    u64 den2 = 0ull;
#pragma unroll 4
    for (int i = 0; i < 196; i++) {
        const ulonglong2* q = (const ulonglong2*)&sT[i][0];
        const ulonglong2 qa = q[0], qb = q[1], qc = q[2], qd = q[3];
        u64 s0 = mul2(av[0], qa.x);
        u64 s1 = mul2(av[1], qa.y);
        s0 = fma2(av[2], qb.x, s0);
        s1 = fma2(av[3], qb.y, s1);
        s0 = fma2(av[4], qc.x, s0);
        s1 = fma2(av[5], qc.y, s1);
        s0 = fma2(av[6], qd.x, s0);
        s1 = fma2(av[7], qd.y, s1);
        s0 = add2(s0, s1);
        float Slo, Shi;
        unpack2(s0, Slo, Shi);
        const u64 ee = pack2(ex2f(Slo), ex2f(Shi));
        acc[0] = fma2(ee, qa.x, acc[0]);
        acc[1] = fma2(ee, qa.y, acc[1]);
        acc[2] = fma2(ee, qb.x, acc[2]);
        acc[3] = fma2(ee, qb.y, acc[3]);
        acc[4] = fma2(ee, qc.x, acc[4]);
        acc[5] = fma2(ee, qc.y, acc[5]);
        acc[6] = fma2(ee, qd.x, acc[6]);
        acc[7] = fma2(ee, qd.y, acc[7]);
        den2 = add2(den2, ee);
    }
    float o[8];
#pragma unroll
    for (int d = 0; d < 8; d++) { float lo, hi; unpack2(acc[d], lo, hi); o[d] = lo + hi; }
    float dl, dh;
    unpack2(den2, dl, dh);
    float* nd = g_num0[ms] + ((size_t)b * LL0 + l) * HH;
    *(float4*)(nd) = make_float4(o[0], o[1], o[2], o[3]);
    *(float4*)(nd + 4) = make_float4(o[4], o[5], o[6], o[7]);
    g_den0[ms][b * LL0 + l] = dl + dh;
}

// ---------------- K3: col direction, pair-packed.
// thread = one m, loops over a 256-wide l chunk in pairs.
// grid (13 mc, 4 ls, 16 b), block 256
__global__ void k_attn_col() {
    __shared__ __align__(16) u64 sT[128][8];  // 8KB
    const int b = blockIdx.z, ls = blockIdx.y, mc = blockIdx.x;
    const int tid = threadIdx.x;
    const float* src = g_x0t + ((size_t)b * LL0 + ls * 256) * HH;
    if (tid < 256) {
        const int m = tid;
        const float4 v0 = *(const float4*)(src + m * 8);
        const float4 v1 = *(const float4*)(src + m * 8 + 4);
        float* f = (float*)&sT[m >> 1][0] + (m & 1);
        f[0] = v0.x; f[2] = v0.y; f[4] = v0.z; f[6] = v0.w;
        f[8] = v1.x; f[10] = v1.y; f[12] = v1.z; f[14] = v1.w;
    }
    __syncthreads();

    const int m = mc * 256 + tid;
    const bool act = (m < LL1);
    const int mm = act ? m : (LL1 - 1);
    const float* a = g_x1t + ((size_t)b * LL1 + mm) * HH;
    u64 av[8];
#pragma unroll
    for (int d = 0; d < 8; d++) { const float s = a[d] * LOG2E; av[d] = pack2(s, s); }

    u64 acc[8] = {0ull, 0ull, 0ull, 0ull, 0ull, 0ull, 0ull, 0ull};
    u64 den2 = 0ull;
#pragma unroll 4
    for (int i = 0; i < 128; i++) {
        const ulonglong2* q = (const ulonglong2*)&sT[i][0];
        const ulonglong2 qa = q[0], qb = q[1], qc = q[2], qd = q[3];
        u64 s0 = mul2(av[0], qa.x);
        u64 s1 = mul2(av[1], qa.y);
        s0 = fma2(av[2], qb.x, s0);
        s1 = fma2(av[3], qb.y, s1);
        s0 = fma2(av[4], qc.x, s0);
        s1 = fma2(av[5], qc.y, s1);
        s0 = fma2(av[6], qd.x, s0);
        s1 = fma2(av[7], qd.y, s1);
        s0 = add2(s0, s1);
        float Slo, Shi;
        unpack2(s0, Slo, Shi);
        const u64 ee = pack2(ex2f(Slo), ex2f(Shi));
        acc[0] = fma2(ee, qa.x, acc[0]);
        acc[1] = fma2(ee, qa.y, acc[1]);
        acc[2] = fma2(ee, qb.x, acc[2]);
        acc[3] = fma2(ee, qb.y, acc[3]);
        acc[4] = fma2(ee, qc.x, acc[4]);
        acc[5] = fma2(ee, qc.y, acc[5]);
        acc[6] = fma2(ee, qd.x, acc[6]);
        acc[7] = fma2(ee, qd.y, acc[7]);
        den2 = add2(den2, ee);
    }
    if (act) {
        float o[8];
#pragma unroll
        for (int d = 0; d < 8; d++) { float lo, hi; unpack2(acc[d], lo, hi); o[d] = lo + hi; }
        float dl, dh;
        unpack2(den2, dl, dh);
        float* nd = g_num1[ls] + ((size_t)b * LL1 + m) * HH;
        *(float4*)(nd) = make_float4(o[0], o[1], o[2], o[3]);
        *(float4*)(nd + 4) = make_float4(o[4], o[5], o[6], o[7]);
        g_den1[ls][b * LL1 + m] = dl + dh;
    }
}

// ---------------- combine0: x0o = fovea(x0t) + x0_1 ----------------
__global__ void k_combine0() {  // grid (4, 16), block 256
    const int b = blockIdx.y;
    const int l = blockIdx.x * 256 + threadIdx.x;
    const size_t base = ((size_t)b * LL0 + l) * HH;
    float num[8] = {0, 0, 0, 0, 0, 0, 0, 0};
    float den = 0.f;
#pragma unroll
    for (int s = 0; s < 8; s++) {
        den += g_den0[s][b * LL0 + l];
        const float4* p = (const float4*)(g_num0[s] + base);
        const float4 v0 = p[0], v1 = p[1];
        num[0] += v0.x; num[1] += v0.y; num[2] += v0.z; num[3] += v0.w;
        num[4] += v1.x; num[5] += v1.y; num[6] += v1.z; num[7] += v1.w;
    }
    const float inv = rcpf(den);
    const float* xt = g_x0t + base;
    const float* S = g_S0 + b * 8;
    float o[8];
#pragma unroll
    for (int d = 0; d < 8; d++) {
        const float t = xt[d];
        o[d] = ex2f(t * LOG2E) * rcpf(S[d]) * t + num[d] * inv;
    }
    float* dst = g_x0o + base;
    *(float4*)(dst) = make_float4(o[0], o[1], o[2], o[3]);
    *(float4*)(dst + 4) = make_float4(o[4], o[5], o[6], o[7]);
}

// ---------------- reduce1: x1_0 = sum(num1)/sum(den1)  (+ fused S1 reduction) ----------------
__global__ void k_reduce1() {  // grid (13, 16), block 256
    __shared__ float sred[8][256];
    const int b = blockIdx.y;
    const int tid = threadIdx.x;
    const int m = blockIdx.x * 256 + tid;
    const bool act = (m < LL1);
    float o[8] = {0, 0, 0, 0, 0, 0, 0, 0};
    if (act) {
        const size_t base = ((size_t)b * LL1 + m) * HH;
        float num[8] = {0, 0, 0, 0, 0, 0, 0, 0};
        float den = 0.f;
#pragma unroll
        for (int s = 0; s < 4; s++) {
            den += g_den1[s][b * LL1 + m];
            const float4* p = (const float4*)(g_num1[s] + base);
            const float4 v0 = p[0], v1 = p[1];
            num[0] += v0.x; num[1] += v0.y; num[2] += v0.z; num[3] += v0.w;
            num[4] += v1.x; num[5] += v1.y; num[6] += v1.z; num[7] += v1.w;
        }
        const float inv = rcpf(den);
#pragma unroll
        for (int d = 0; d < 8; d++) o[d] = num[d] * inv;
        float* dst = g_x10 + base;
        *(float4*)(dst) = make_float4(o[0], o[1], o[2], o[3]);
        *(float4*)(dst + 4) = make_float4(o[4], o[5], o[6], o[7]);
    }
    // fused S1[b,d] += sum over this block of exp(x10)
#pragma unroll
    for (int d = 0; d < 8; d++) sred[d][tid] = act ? ex2f(o[d] * LOG2E) : 0.f;
    __syncthreads();
    for (int off = 128; off; off >>= 1) {
        if (tid < off)
#pragma unroll
            for (int d = 0; d < 8; d++) sred[d][tid] += sred[d][tid + off];
        __syncthreads();
    }
    if (tid < 8) atomicAdd(&g_S1[b * 8 + tid], sred[tid][0]);
}

// ---------------- combine1: x1o = fovea(x1_0) + x1t ----------------
__global__ void k_combine1() {  // grid (13, 16), block 256
    const int b = blockIdx.y;
    const int m = blockIdx.x * 256 + threadIdx.x;
    if (m >= LL1) return;
    const size_t base = ((size_t)b * LL1 + m) * HH;
    const float* xt = g_x1t + base;
    const float* x10 = g_x10 + base;
    const float* S = g_S1 + b * 8;
    float o[8];
#pragma unroll
    for (int d = 0; d < 8; d++) {
        const float t = x10[d];
        o[d] = ex2f(t * LOG2E) * rcpf(S[d]) * t + xt[d];
    }
    float* dst = g_x1o + base;
    *(float4*)(dst) = make_float4(o[0], o[1], o[2], o[3]);
    *(float4*)(dst + 4) = make_float4(o[4], o[5], o[6], o[7]);
}

// ---------------- output projections (fused transpose) ----------------
__global__ void k_out0(const float* __restrict__ W1, const float* __restrict__ b1,
                       float* __restrict__ out) {
    const int b = blockIdx.z, lcb = blockIdx.y, ccb = blockIdx.x;
    const int w = threadIdx.x >> 5, lane = threadIdx.x & 31;
    const int l0 = lcb * 128 + lane * 4;
    const float* xo = g_x0o + ((size_t)b * LL0 + l0) * HH;
    float xr[4][8];
#pragma unroll
    for (int r = 0; r < 4; r++) {
        const float4 v0 = *(const float4*)(xo + (size_t)r * HH);
        const float4 v1 = *(const float4*)(xo + (size_t)r * HH + 4);
        xr[r][0] = v0.x; xr[r][1] = v0.y; xr[r][2] = v0.z; xr[r][3] = v0.w;
        xr[r][4] = v1.x; xr[r][5] = v1.y; xr[r][6] = v1.z; xr[r][7] = v1.w;
    }
    float* ob = out + (size_t)b * CC * LL0;
    for (int j = 0; j < 12; j++) {
        const int c = ccb * 96 + w * 12 + j;
        float wv[8];
#pragma unroll
        for (int k = 0; k < 8; k++) wv[k] = __ldg(&W1[k * CC + c]);
        const float bias = __ldg(&b1[c]);
        float o[4];
#pragma unroll
        for (int r = 0; r < 4; r++) {
            float acc = bias;
#pragma unroll
            for (int k = 0; k < 8; k++) acc += xr[r][k] * wv[k];
            o[r] = acc;
        }
        __stcs((float4*)(ob + (size_t)c * LL0 + l0), make_float4(o[0], o[1], o[2], o[3]));
    }
}

__global__ void k_out1(const float* __restrict__ W2, const float* __restrict__ b2,
                       float* __restrict__ out) {
    const int b = blockIdx.z, lcb = blockIdx.y, ccb = blockIdx.x;
    const int w = threadIdx.x >> 5, lane = threadIdx.x & 31;
    const int l0 = lcb * 128 + lane * 4;
    const bool active = (l0 < LL1);
    float xr[4][8];
    if (active) {
        const float* xo = g_x1o + ((size_t)b * LL1 + l0) * HH;
#pragma unroll
        for (int r = 0; r < 4; r++) {
            const float4 v0 = *(const float4*)(xo + (size_t)r * HH);
            const float4 v1 = *(const float4*)(xo + (size_t)r * HH + 4);
            xr[r][0] = v0.x; xr[r][1] = v0.y; xr[r][2] = v0.z; xr[r][3] = v0.w;
            xr[r][4] = v1.x; xr[r][5] = v1.y; xr[r][6] = v1.z; xr[r][7] = v1.w;
        }
    }
    float* ob = out + (size_t)BB * CC * LL0 + (size_t)b * CC * LL1;
    for (int j = 0; j < 12; j++) {
        const int c = ccb * 96 + w * 12 + j;
        float wv[8];
#pragma unroll
        for (int k = 0; k < 8; k++) wv[k] = __ldg(&W2[k * CC + c]);
        const float bias = __ldg(&b2[c]);
        if (active) {
            float o[4];
#pragma unroll
            for (int r = 0; r < 4; r++) {
                float acc = bias;
#pragma unroll
                for (int k = 0; k < 8; k++) acc += xr[r][k] * wv[k];
                o[r] = acc;
            }
            __stcs((float4*)(ob + (size_t)c * LL1 + l0), make_float4(o[0], o[1], o[2], o[3]));
        }
    }
}

extern "C" void kernel_launch(void* const* d_in, const int* in_sizes, int n_in,
                              void* d_out, int out_size) {
    const float* x   = (const float*)d_in[0];
    const float* W00 = (const float*)d_in[1];
    const float* b00 = (const float*)d_in[2];
    const float* W01 = (const float*)d_in[3];
    const float* b01 = (const float*)d_in[4];
    const float* W1  = (const float*)d_in[5];
    const float* b1  = (const float*)d_in[6];
    const float* W2  = (const float*)d_in[7];
    const float* b2  = (const float*)d_in[8];
    float* out = (float*)d_out;

    k_zero<<<1, 256>>>();
    k_proj<<<2080, 256>>>(x, W00, b00, W01, b01);
    k_attn_row<<<dim3(4, 8, 16), 256>>>();
    k_attn_col<<<dim3(13, 4, 16), 256>>>();
    k_combine0<<<dim3(4, 16), 256>>>();
    k_reduce1<<<dim3(13, 16), 256>>>();
    k_combine1<<<dim3(13, 16), 256>>>();
    k_out0<<<dim3(8, 8, 16), 256>>>(W1, b1, out);
    k_out1<<<dim3(8, 25, 16), 256>>>(W2, b2, out);
}